// round 15
// baseline (speedup 1.0000x reference)
#include <cuda_runtime.h>
#include <math.h>

// Problem constants (fixed by the dataset: B=2, C=1, T=8640, F=8, HID=16)
#define RNUM 2          // B*C rows
#define BB   2
#define FF   8
#define HIDN 16
#define TT   8640
#define TT1  8641
#define NB   256        // value buckets
#define NSEG 96
#define SEGLEN 90       // TT / NSEG
#define CHNK 23         // ceil(SEGLEN/4)
#define CAP  512        // per-warp sub-bin tag capacity (bytes)
#define MMBLK 17        // min/max partial blocks per row (17*512 >= 8640)

// ---------- device scratch (static; no allocations) ----------
__device__ int   g_w, g_k;
__device__ float g_lo[RNUM], g_hi[RNUM];
__device__ float g_plo[RNUM * MMBLK], g_phi[RNUM * MMBLK];
__device__ unsigned       g_segHist[RNUM * NSEG * NB];     // counts -> (k_scan) seg bases
__device__ unsigned       g_bucketBase[RNUM * (NB + 1)];   // exclusive cumulative histogram
__device__ __align__(16) unsigned short g_H[(size_t)RNUM * TT1 * NB]; // prefix counts (uint16)
__device__ float          g_L[RNUM * TT];                  // bucket-sorted values
__device__ unsigned short g_Lid[RNUM * TT];                // fine (16-bit) bucket id per L elem

__device__ __forceinline__ float row_scale_from(float lo, float hi) {
    float d = hi - lo;
    return d > 0.f ? 255.0f / d : 0.f;
}
__device__ __forceinline__ int bucket_of(float v, float lo, float sc) {
    int j = (int)((v - lo) * sc);
    j = j < 0 ? 0 : j;
    return j > NB - 1 ? NB - 1 : j;
}
// reduce the MMBLK partials of row r (fixed order -> bit-identical everywhere)
__device__ __forceinline__ void reduce_partials(int r, float& lo, float& hi) {
    float l = g_plo[r * MMBLK], h = g_phi[r * MMBLK];
#pragma unroll
    for (int i = 1; i < MMBLK; i++) {
        l = fminf(l, g_plo[r * MMBLK + i]);
        h = fmaxf(h, g_phi[r * MMBLK + i]);
    }
    lo = l; hi = h;
}

// ---------- K0: partial min/max (grid-parallel) + MLP block ----------
__global__ __launch_bounds__(512) void k_mm(const float* __restrict__ x,
                     const float* __restrict__ meta,
                     const float* __restrict__ w1, const float* __restrict__ b1,
                     const float* __restrict__ w2, const float* __restrict__ b2,
                     int n_out) {
    int blk = blockIdx.x;
    int t = threadIdx.x;
    if (blk == RNUM * MMBLK) {
        if (t != 0) return;
        int wmax = 0;
        for (int bb = 0; bb < BB; bb++) {
            float s = b2[0];
            for (int j = 0; j < HIDN; j++) {
                float h = b1[j];
                for (int f = 0; f < FF; f++) h = fmaf(meta[bb * FF + f], w1[f * HIDN + j], h);
                h = h > 0.f ? h : 0.f;
                s = fmaf(h, w2[j], s);
            }
            float factor;
            if (s >= 0.f) factor = 1.f / (1.f + expf(-s));
            else { float e = expf(s); factor = e / (1.f + e); }
            float hours = 4.0f + factor * 44.0f;
            int samp = (int)(hours * 360.0f);
            if (samp > wmax) wmax = samp;
        }
        int w = wmax < TT ? wmax : TT;
        int exp_par = (n_out == TT1) ? 0 : 1;   // n_out = TT+1 - (w&1)
        if ((w & 1) != exp_par) { if (w < TT) w++; else w--; }
        g_w = w;
        g_k = (w - 1) >> 1;
        return;
    }
    int r = (blk >= MMBLK) ? 1 : 0;          // RNUM == 2
    int lb = blk - r * MMBLK;
    int p = lb * 512 + t;
    float lo = 1e30f, hi = -1e30f;
    if (p < TT) { float v = x[r * TT + p]; lo = v; hi = v; }
#pragma unroll
    for (int off = 16; off > 0; off >>= 1) {
        lo = fminf(lo, __shfl_xor_sync(0xffffffffu, lo, off));
        hi = fmaxf(hi, __shfl_xor_sync(0xffffffffu, hi, off));
    }
    __shared__ float rlo[16], rhi[16];
    int lane = t & 31, warp = t >> 5;
    if (lane == 0) { rlo[warp] = lo; rhi[warp] = hi; }
    __syncthreads();
    if (t == 0) {
        float l = rlo[0], h = rhi[0];
#pragma unroll
        for (int i = 1; i < 16; i++) { l = fminf(l, rlo[i]); h = fmaxf(h, rhi[i]); }
        g_plo[blk] = l; g_phi[blk] = h;
    }
}

// ---------- K1: per-segment histograms (warp per segment, 8 segs/block) ----------
__global__ __launch_bounds__(256) void k_hist(const float* __restrict__ x) {
    int t = threadIdx.x;
    int warp = t >> 5, lane = t & 31;
    int seg_global = blockIdx.x * 8 + warp;      // 0 .. RNUM*NSEG-1
    int r = (seg_global >= NSEG) ? 1 : 0;        // RNUM == 2
    int s = seg_global - r * NSEG;

    __shared__ float s_lo, s_sc;
    if (t == 0) {
        float l, h; reduce_partials(r, l, h);
        s_lo = l; s_sc = row_scale_from(l, h);
    }
    __shared__ unsigned hist[8][NB];
#pragma unroll
    for (int i = 0; i < NB / 32; i++) hist[warp][i * 32 + lane] = 0;
    __syncthreads();

    float lo = s_lo, sc = s_sc;
    const float* xs = x + r * TT + s * SEGLEN;
    for (int p = lane; p < SEGLEN; p += 32)
        atomicAdd(&hist[warp][bucket_of(xs[p], lo, sc)], 1u);
    __syncwarp();
    unsigned* dst = g_segHist + (size_t)(r * NSEG + s) * NB;
#pragma unroll
    for (int i = 0; i < NB / 32; i++) dst[i * 32 + lane] = hist[warp][i * 32 + lane];
}

// ---------- K2: scan segments per bin (register-resident) + bucket bases
//              + publish final row min/max ----------
__global__ void k_scan() {
    int r = blockIdx.x, j = threadIdx.x;
    if (j == 0) {   // publish finals for k_fill / k_select (same reduce order -> identical)
        float l, h; reduce_partials(r, l, h);
        g_lo[r] = l; g_hi[r] = h;
    }
    size_t base = (size_t)r * NSEG * NB + j;
    unsigned v[NSEG];
#pragma unroll
    for (int s = 0; s < NSEG; s++) v[s] = g_segHist[base + (size_t)s * NB];
    unsigned run = 0;
#pragma unroll
    for (int s = 0; s < NSEG; s++) { unsigned t = v[s]; v[s] = run; run += t; }
#pragma unroll
    for (int s = 0; s < NSEG; s++) g_segHist[base + (size_t)s * NB] = v[s];

    __shared__ unsigned tot[NB];
    tot[j] = run;
    __syncthreads();
    // shuffle-based scan over 256 bins
    int lane = j & 31, w8 = j >> 5;
    unsigned c = run;
#pragma unroll
    for (int off = 1; off < 32; off <<= 1) {
        unsigned t2 = __shfl_up_sync(0xffffffffu, c, off);
        if (lane >= off) c += t2;
    }
    __shared__ unsigned wsum[8];
    if (lane == 31) wsum[w8] = c;
    __syncthreads();
    unsigned add = 0;
    for (int i = 0; i < w8; i++) add += wsum[i];
    unsigned incl = c + add;
    g_bucketBase[r * (NB + 1) + j] = incl - run;     // exclusive
    if (j == NB - 1) g_bucketBase[r * (NB + 1) + NB] = incl;
    (void)tot;
}

// ---------- K3: fill prefix table H (ushort4 stores) and sorted list L(+ids) ----------
__global__ __launch_bounds__(256) void k_fill(const float* __restrict__ x) {
    int r = blockIdx.x / NSEG, s = blockIdx.x % NSEG;
    int t = threadIdx.x;
    int bg = t & 63;          // bucket group: buckets 4bg .. 4bg+3
    int c  = t >> 6;          // position chunk 0..3

    __shared__ unsigned char bj[SEGLEN];
    __shared__ float xv[SEGLEN];
    __shared__ unsigned short fid[SEGLEN];
    __shared__ unsigned short scnt[4][NB];   // per-chunk per-bucket counts
    __shared__ float s_lo, s_sc256;
    if (t == 0) {
        float l = g_lo[r];
        s_lo = l; s_sc256 = row_scale_from(l, g_hi[r]) * 256.0f;
    }
    __syncthreads();
    if (t < SEGLEN) {
        float v = x[r * TT + s * SEGLEN + t];
        xv[t] = v;
        // fine id: floor((v-lo)*sc*256); exactly fine>>8 == bucket_of(v)
        int f = (int)((v - s_lo) * s_sc256);
        f = f < 0 ? 0 : (f > 65279 ? 65279 : f);
        fid[t] = (unsigned short)f;
        bj[t] = (unsigned char)(f >> 8);
    }
    __syncthreads();

    int p0 = c * CHNK, p1 = p0 + CHNK;
    if (p1 > SEGLEN) p1 = SEGLEN;

    // phase 1: count own buckets in own chunk
    int cnt[4] = {0, 0, 0, 0};
    for (int p = p0; p < p1; p++) {
        int b = bj[p];
        if ((b >> 2) == bg) cnt[b & 3]++;
    }
#pragma unroll
    for (int q = 0; q < 4; q++) scnt[c][4 * bg + q] = (unsigned short)cnt[q];
    __syncthreads();

    // phase 2: chunk-start running counts = global seg base + earlier chunks
    unsigned run[4];
    const unsigned* segb = g_segHist + (size_t)(r * NSEG + s) * NB + 4 * bg;
#pragma unroll
    for (int q = 0; q < 4; q++) run[q] = segb[q];
    for (int cc = 0; cc < c; cc++)
#pragma unroll
        for (int q = 0; q < 4; q++) run[q] += scnt[cc][4 * bg + q];

    unsigned bb[4];
    const unsigned* bbp = g_bucketBase + r * (NB + 1) + 4 * bg;
#pragma unroll
    for (int q = 0; q < 4; q++) bb[q] = bbp[q];

    // phase 3: write packed H row-slices + scatter L and fine ids
    size_t hbase = ((size_t)r * TT1 + (size_t)s * SEGLEN) * NB + 4 * bg;
    float* Lr = g_L + r * TT;
    unsigned short* Ir = g_Lid + r * TT;
    for (int p = p0; p < p1; p++) {
        ushort4 v;
        v.x = (unsigned short)run[0]; v.y = (unsigned short)run[1];
        v.z = (unsigned short)run[2]; v.w = (unsigned short)run[3];
        *(ushort4*)(g_H + hbase + (size_t)p * NB) = v;
        int b = bj[p];
        if ((b >> 2) == bg) {
            int q = b & 3;
            unsigned pos = bb[q] + run[q];
            Lr[pos] = xv[p];
            Ir[pos] = fid[p];
            run[q]++;
        }
    }
    if (s == NSEG - 1 && c == 3) {
        ushort4 v;
        v.x = (unsigned short)run[0]; v.y = (unsigned short)run[1];
        v.z = (unsigned short)run[2]; v.w = (unsigned short)run[3];
        *(ushort4*)(g_H + ((size_t)r * TT1 + TT) * NB + 4 * bg) = v;
    }
}

// ---------- K4: one warp per window -> exact median (two-level histogram) ----------
__global__ __launch_bounds__(256, 6) void k_select(const float* __restrict__ x,
                                                   float* __restrict__ out, int n_out) {
    int warp = threadIdx.x >> 5, lane = threadIdx.x & 31;
    int gw = blockIdx.x * 8 + warp;
    if (gw >= RNUM * n_out) return;
    int r = (gw >= n_out) ? 1 : 0;           // RNUM == 2: no integer division
    int i = gw - (r ? n_out : 0);

    int w = g_w, k = g_k, pad = w >> 1;
    int start = i - pad;
    int a = start > 0 ? start : 0;
    int b = (start + w < TT) ? (start + w) : TT;
    int cL = start < 0 ? -start : 0;
    int cR = (start + w > TT) ? (start + w - TT) : 0;

    float lo = g_lo[r], sc = row_scale_from(lo, g_hi[r]);
    float x0  = x[r * TT];
    float xT1 = x[r * TT + TT - 1];
    int j0 = bucket_of(x0, lo, sc), jT = bucket_of(xT1, lo, sc);

    // ---- top-level bucket find, packed-halfword arithmetic ----
    const uint4* pa = (const uint4*)(g_H + ((size_t)r * TT1 + a) * NB);
    const uint4* pb = (const uint4*)(g_H + ((size_t)r * TT1 + b) * NB);
    uint4 A = pa[lane], B = pb[lane];
    unsigned dp[4] = {B.x - A.x, B.y - A.y, B.z - A.z, B.w - A.w};
    if ((j0 >> 3) == lane) dp[(j0 >> 1) & 3] += (unsigned)cL << ((j0 & 1) * 16);
    if ((jT >> 3) == lane) dp[(jT >> 1) & 3] += (unsigned)cR << ((jT & 1) * 16);
    unsigned uv = dp[0] + dp[1] + dp[2] + dp[3];
    int S = (int)((uv & 0xFFFFu) + (uv >> 16));   // this lane's 8-bin total

    int cum = S;
#pragma unroll
    for (int off = 1; off < 32; off <<= 1) {
        int t2 = __shfl_up_sync(0xffffffffu, cum, off);
        if (lane >= off) cum += t2;
    }
    unsigned bal = __ballot_sync(0xffffffffu, cum >= k + 1);
    int ln = __ffs(bal) - 1;
    int jstar = 0, base = 0, haj = 0, hbj = 0;
    if (lane == ln) {
        int run = cum - S;
        bool fnd = false;
        const unsigned* Aw = &A.x;
        const unsigned* Bw = &B.x;
#pragma unroll
        for (int t = 0; t < 8; t++) {
            int sh = (t & 1) * 16;
            int dt = (int)((dp[t >> 1] >> sh) & 0xFFFFu);
            int nr = run + dt;
            if (!fnd && nr >= k + 1) {
                jstar = lane * 8 + t;
                base = run;
                haj = (int)((Aw[t >> 1] >> sh) & 0xFFFFu);
                hbj = (int)((Bw[t >> 1] >> sh) & 0xFFFFu);
                fnd = true;
            }
            if (!fnd) run = nr;
        }
    }
    jstar = __shfl_sync(0xffffffffu, jstar, ln);
    base  = __shfl_sync(0xffffffffu, base,  ln);
    haj   = __shfl_sync(0xffffffffu, haj,   ln);
    hbj   = __shfl_sync(0xffffffffu, hbj,   ln);

    int r_in = k - base;                      // residual rank inside bucket jstar (with dups)
    int m = hbj - haj;                        // real slice length
    unsigned loS = g_bucketBase[r * (NB + 1) + jstar] + (unsigned)haj;
    int eL = (j0 == jstar) ? cL : 0;
    int eR = (jT == jstar) ? cR : 0;
    const float*          Ls = g_L   + r * TT + loS;
    const unsigned short* Is = g_Lid + r * TT + loS;

    __shared__ unsigned      hist[8][NB];
    __shared__ float         cand[8][32];
    __shared__ unsigned char subs[8][CAP];

    float sc256 = sc * 256.0f;
    int jsh = jstar << 8;
#define SUB_OF(v_) ({ int f_ = (int)(((v_) - lo) * sc256) - jsh;                 \
                      f_ = f_ < 0 ? 0 : (f_ > 255 ? 255 : f_); f_; })

    if (m <= CAP) {
#pragma unroll
        for (int q = 0; q < 8; q++) hist[warp][q * 32 + lane] = 0;
        __syncwarp();
        for (int t = lane; t < m; t += 32) {
            int sb = (int)Is[t] - jsh;
            subs[warp][t] = (unsigned char)sb;
            atomicAdd(&hist[warp][sb], 1u);
        }
        int sub0 = -1, subT = -1;
        if (eL > 0) sub0 = SUB_OF(x0);
        if (eR > 0) subT = SUB_OF(xT1);
        if (lane == 0) {
            if (eL > 0) atomicAdd(&hist[warp][sub0], (unsigned)eL);
            if (eR > 0) atomicAdd(&hist[warp][subT], (unsigned)eR);
        }
        __syncwarp();

        // ---- sub-bin scan (lane owns 8 bins; 2x LDS.128) ----
        const uint4* hp = (const uint4*)&hist[warp][lane * 8];
        uint4 h0 = hp[0], h1 = hp[1];
        int d2[8] = {(int)h0.x, (int)h0.y, (int)h0.z, (int)h0.w,
                     (int)h1.x, (int)h1.y, (int)h1.z, (int)h1.w};
        int S2 = d2[0] + d2[1] + d2[2] + d2[3] + d2[4] + d2[5] + d2[6] + d2[7];
        int cum2 = S2;
#pragma unroll
        for (int off = 1; off < 32; off <<= 1) {
            int t2 = __shfl_up_sync(0xffffffffu, cum2, off);
            if (lane >= off) cum2 += t2;
        }
        unsigned bal2 = __ballot_sync(0xffffffffu, cum2 >= r_in + 1);
        int ln2 = __ffs(bal2) - 1;
        int sstar = 0, base2 = 0;
        if (lane == ln2) {
            int run2 = cum2 - S2;
            bool fnd = false;
#pragma unroll
            for (int q = 0; q < 8; q++) {
                int nr = run2 + d2[q];
                if (!fnd && nr >= r_in + 1) { sstar = lane * 8 + q; base2 = run2; fnd = true; }
                if (!fnd) run2 = nr;
            }
        }
        sstar = __shfl_sync(0xffffffffu, sstar, ln2);
        base2 = __shfl_sync(0xffffffffu, base2, ln2);
        int r2 = r_in - base2;

        // ---- gather slice members of sub-bin sstar (byte compare) ----
        int cnt = 0;
        unsigned char sb8 = (unsigned char)sstar;
        for (int cc = 0; cc * 32 < m; cc++) {
            int idx = cc * 32 + lane;
            bool act = idx < m;
            bool match = act && (subs[warp][idx] == sb8);
            unsigned bm = __ballot_sync(0xffffffffu, match);
            int pos = cnt + __popc(bm & ((1u << lane) - 1u));
            if (match && pos < 32) cand[warp][pos] = Ls[idx];
            cnt += __popc(bm);
        }
        __syncwarp();

        if (cnt <= 32) {
            int vl = (eL > 0 && sub0 == sstar) ? eL : 0;
            int vr = (eR > 0 && subT == sstar) ? eR : 0;
            float c = (lane < cnt) ? cand[warp][lane] : 0.f;
            int lt = 0, eq = 0;
            for (int t = 0; t < cnt; t++) {
                float rv = cand[warp][t];
                lt += rv < c;
                eq += rv == c;
            }
            lt += vl * (x0 < c) + vr * (xT1 < c);
            eq += vl * (x0 == c) + vr * (xT1 == c);
            bool win = (lane < cnt) && (lt <= r2) && (r2 < lt + eq);
            unsigned bw = __ballot_sync(0xffffffffu, win);
            float ans = __shfl_sync(0xffffffffu, c, __ffs(bw) - 1);
            if (lane == 0) out[(size_t)r * n_out + i] = ans;
            return;
        }
        __syncwarp();
    }

    // ---- fallback: per-candidate counting over global slice (rare) ----
    float ans = 0.f;
    bool found = false;
    for (int cc = 0; cc * 32 < m && !found; cc++) {
        int idx = cc * 32 + lane;
        bool act = idx < m;
        float c = act ? Ls[idx] : 0.f;
        int lt = 0, eq = 0;
        for (int t = 0; t < m; t++) {
            float rv = Ls[t];
            lt += rv < c;
            eq += rv == c;
        }
        lt += eL * (x0 < c) + eR * (xT1 < c);
        eq += eL * (x0 == c) + eR * (xT1 == c);
        bool win = act && (lt <= r_in) && (r_in < lt + eq);
        unsigned bw = __ballot_sync(0xffffffffu, win);
        if (bw) { ans = __shfl_sync(0xffffffffu, c, __ffs(bw) - 1); found = true; }
    }
    if (lane == 0) out[(size_t)r * n_out + i] = ans;
#undef SUB_OF
}

// ---------- launch ----------
extern "C" void kernel_launch(void* const* d_in, const int* in_sizes, int n_in,
                              void* d_out, int out_size) {
    const float* att  = (const float*)d_in[0];
    const float* meta = (const float*)d_in[1];
    const float* w1   = (const float*)d_in[2];
    const float* b1   = (const float*)d_in[3];
    const float* w2   = (const float*)d_in[4];
    const float* b2   = (const float*)d_in[5];
    float* out = (float*)d_out;
    (void)in_sizes; (void)n_in;

    int n_out = out_size / RNUM;

    k_mm<<<RNUM * MMBLK + 1, 512>>>(att, meta, w1, b1, w2, b2, n_out);
    k_hist<<<RNUM * NSEG / 8, 256>>>(att);
    k_scan<<<RNUM, 256>>>();
    k_fill<<<RNUM * NSEG, 256>>>(att);

    int total_warps = RNUM * n_out;
    int blocks = (total_warps + 7) / 8;
    k_select<<<blocks, 256>>>(att, out, n_out);
}

// round 16
// speedup vs baseline: 1.1166x; 1.1166x over previous
#include <cuda_runtime.h>
#include <math.h>

// Problem constants (fixed by the dataset: B=2, C=1, T=8640, F=8, HID=16)
#define RNUM 2          // B*C rows
#define BB   2
#define FF   8
#define HIDN 16
#define TT   8640
#define TT1  8641
#define NB   256        // value buckets
#define NSEG 96
#define SEGLEN 90       // TT / NSEG
#define CHNK2 12        // ceil(SEGLEN/8) positions per chunk in k_fill
#define CAP  512        // per-warp sub-bin tag capacity (bytes)

// Static monotone quantizer over [0, 24): data is N(10,2)-ish so buckets stay
// balanced; correctness does NOT depend on balance (exact in-bucket ranking +
// CAP fallback handle any distribution; clamping keeps the map monotone).
#define SC    (256.0f / 24.0f)
#define SC256 (SC * 256.0f)     // exactly 256*SC in fp32 (power-of-2 scale)

// ---------- device scratch (static; no allocations) ----------
__device__ int   g_w, g_k;
__device__ unsigned       g_segHist[RNUM * NSEG * NB];     // counts -> (k_scan) seg bases
__device__ unsigned       g_bucketBase[RNUM * (NB + 1)];   // exclusive cumulative histogram
__device__ __align__(16) unsigned short g_H[(size_t)RNUM * TT1 * NB]; // prefix counts (uint16)
__device__ float          g_L[RNUM * TT];                  // bucket-sorted values
__device__ unsigned short g_Lid[RNUM * TT];                // fine (16-bit) bucket id per L elem

// fine id: floor(v*SC256) clamped; bucket = fine>>8 (exactly == floor(v*SC) clamped,
// since fl(v*SC256) = 256*fl(v*SC) bit-exactly, and both clamps agree at the ends)
__device__ __forceinline__ int fine_of(float v) {
    int f = (int)(v * SC256);
    f = f < 0 ? 0 : (f > 65535 ? 65535 : f);
    return f;
}
__device__ __forceinline__ int bucket_fixed(float v) {
    int j = (int)(v * SC);
    j = j < 0 ? 0 : (j > NB - 1 ? NB - 1 : j);
    return j;
}

// ---------- K1: per-segment histograms (warp per segment, 8 segs/block)
//             extra block runs the tiny MLP; NO cross-kernel dependency ----------
__global__ __launch_bounds__(256) void k_hist(const float* __restrict__ x,
                     const float* __restrict__ meta,
                     const float* __restrict__ w1, const float* __restrict__ b1,
                     const float* __restrict__ w2, const float* __restrict__ b2,
                     int n_out) {
    int t = threadIdx.x;
    if (blockIdx.x == RNUM * NSEG / 8) {
        if (t != 0) return;
        int wmax = 0;
        for (int bb = 0; bb < BB; bb++) {
            float s = b2[0];
            for (int j = 0; j < HIDN; j++) {
                float h = b1[j];
                for (int f = 0; f < FF; f++) h = fmaf(meta[bb * FF + f], w1[f * HIDN + j], h);
                h = h > 0.f ? h : 0.f;
                s = fmaf(h, w2[j], s);
            }
            float factor;
            if (s >= 0.f) factor = 1.f / (1.f + expf(-s));
            else { float e = expf(s); factor = e / (1.f + e); }
            float hours = 4.0f + factor * 44.0f;
            int samp = (int)(hours * 360.0f);
            if (samp > wmax) wmax = samp;
        }
        int w = wmax < TT ? wmax : TT;
        int exp_par = (n_out == TT1) ? 0 : 1;   // n_out = TT+1 - (w&1)
        if ((w & 1) != exp_par) { if (w < TT) w++; else w--; }
        g_w = w;
        g_k = (w - 1) >> 1;
        return;
    }
    int warp = t >> 5, lane = t & 31;
    int seg_global = blockIdx.x * 8 + warp;      // 0 .. RNUM*NSEG-1
    int r = (seg_global >= NSEG) ? 1 : 0;        // RNUM == 2
    int s = seg_global - r * NSEG;

    __shared__ unsigned hist[8][NB];
#pragma unroll
    for (int i = 0; i < NB / 32; i++) hist[warp][i * 32 + lane] = 0;
    __syncwarp();
    const float* xs = x + r * TT + s * SEGLEN;
    for (int p = lane; p < SEGLEN; p += 32)
        atomicAdd(&hist[warp][fine_of(xs[p]) >> 8], 1u);
    __syncwarp();
    unsigned* dst = g_segHist + (size_t)(r * NSEG + s) * NB;
#pragma unroll
    for (int i = 0; i < NB / 32; i++) dst[i * 32 + lane] = hist[warp][i * 32 + lane];
}

// ---------- K2: scan segments per bin (register-resident) + bucket bases ----------
__global__ void k_scan() {
    int r = blockIdx.x, j = threadIdx.x;
    size_t base = (size_t)r * NSEG * NB + j;
    unsigned v[NSEG];
#pragma unroll
    for (int s = 0; s < NSEG; s++) v[s] = g_segHist[base + (size_t)s * NB];
    unsigned run = 0;
#pragma unroll
    for (int s = 0; s < NSEG; s++) { unsigned t = v[s]; v[s] = run; run += t; }
#pragma unroll
    for (int s = 0; s < NSEG; s++) g_segHist[base + (size_t)s * NB] = v[s];

    // shuffle-based exclusive scan over 256 bins
    int lane = j & 31, w8 = j >> 5;
    unsigned c = run;
#pragma unroll
    for (int off = 1; off < 32; off <<= 1) {
        unsigned t2 = __shfl_up_sync(0xffffffffu, c, off);
        if (lane >= off) c += t2;
    }
    __shared__ unsigned wsum[8];
    if (lane == 31) wsum[w8] = c;
    __syncthreads();
    unsigned add = 0;
    for (int i = 0; i < w8; i++) add += wsum[i];
    unsigned incl = c + add;
    g_bucketBase[r * (NB + 1) + j] = incl - run;     // exclusive
    if (j == NB - 1) g_bucketBase[r * (NB + 1) + NB] = incl;
}

// ---------- K3: fill prefix table H (uint4 stores) and sorted list L(+ids) ----------
// thread layout: bg = t&31 owns buckets 8bg..8bg+7; c = t>>5 owns chunk c (12 pos)
__global__ __launch_bounds__(256) void k_fill(const float* __restrict__ x) {
    int r = blockIdx.x / NSEG, s = blockIdx.x % NSEG;
    int t = threadIdx.x;
    int bg = t & 31;
    int c  = t >> 5;

    __shared__ unsigned char bj[SEGLEN];
    __shared__ float xv[SEGLEN];
    __shared__ unsigned short fid[SEGLEN];
    __shared__ unsigned short scnt[8][NB];   // per-chunk per-bucket counts
    if (t < SEGLEN) {
        float v = x[r * TT + s * SEGLEN + t];
        xv[t] = v;
        int f = fine_of(v);
        fid[t] = (unsigned short)f;
        bj[t] = (unsigned char)(f >> 8);
    }
    __syncthreads();

    int p0 = c * CHNK2, p1 = p0 + CHNK2;
    if (p1 > SEGLEN) p1 = SEGLEN;

    // phase 1: count own 8 buckets in own chunk
    int cnt[8] = {0, 0, 0, 0, 0, 0, 0, 0};
    for (int p = p0; p < p1; p++) {
        int b = bj[p];
        if ((b >> 3) == bg) cnt[b & 7]++;
    }
#pragma unroll
    for (int q = 0; q < 8; q++) scnt[c][8 * bg + q] = (unsigned short)cnt[q];
    __syncthreads();

    // phase 2: chunk-start running counts = global seg base + earlier chunks
    unsigned run[8];
    const unsigned* segb = g_segHist + (size_t)(r * NSEG + s) * NB + 8 * bg;
#pragma unroll
    for (int q = 0; q < 8; q++) run[q] = segb[q];
    for (int cc = 0; cc < c; cc++)
#pragma unroll
        for (int q = 0; q < 8; q++) run[q] += scnt[cc][8 * bg + q];

    unsigned bb[8];
    const unsigned* bbp = g_bucketBase + r * (NB + 1) + 8 * bg;
#pragma unroll
    for (int q = 0; q < 8; q++) bb[q] = bbp[q];

    // phase 3: write packed H row-slices (one STG.128 per position) + scatter L
    size_t hbase = ((size_t)r * TT1 + (size_t)s * SEGLEN) * NB + 8 * bg;
    float* Lr = g_L + r * TT;
    unsigned short* Ir = g_Lid + r * TT;
    for (int p = p0; p < p1; p++) {
        uint4 v;
        v.x = run[0] | (run[1] << 16);
        v.y = run[2] | (run[3] << 16);
        v.z = run[4] | (run[5] << 16);
        v.w = run[6] | (run[7] << 16);
        *(uint4*)(g_H + hbase + (size_t)p * NB) = v;
        int b = bj[p];
        if ((b >> 3) == bg) {
            int q = b & 7;
            unsigned pos = bb[q] + run[q];
            Lr[pos] = xv[p];
            Ir[pos] = fid[p];
            run[q]++;
        }
    }
    if (s == NSEG - 1 && c == 7) {
        uint4 v;
        v.x = run[0] | (run[1] << 16);
        v.y = run[2] | (run[3] << 16);
        v.z = run[4] | (run[5] << 16);
        v.w = run[6] | (run[7] << 16);
        *(uint4*)(g_H + ((size_t)r * TT1 + TT) * NB + 8 * bg) = v;
    }
}

// ---------- K4: one warp per window -> exact median (two-level histogram) ----------
__global__ __launch_bounds__(256, 6) void k_select(const float* __restrict__ x,
                                                   float* __restrict__ out, int n_out) {
    int warp = threadIdx.x >> 5, lane = threadIdx.x & 31;
    int gw = blockIdx.x * 8 + warp;
    if (gw >= RNUM * n_out) return;
    int r = (gw >= n_out) ? 1 : 0;           // RNUM == 2: no integer division
    int i = gw - (r ? n_out : 0);

    int w = g_w, k = g_k, pad = w >> 1;
    int start = i - pad;
    int a = start > 0 ? start : 0;
    int b = (start + w < TT) ? (start + w) : TT;
    int cL = start < 0 ? -start : 0;
    int cR = (start + w > TT) ? (start + w - TT) : 0;

    float x0  = x[r * TT];
    float xT1 = x[r * TT + TT - 1];
    int f0 = fine_of(x0), fT = fine_of(xT1);
    int j0 = f0 >> 8, jT = fT >> 8;

    // ---- top-level bucket find, packed-halfword arithmetic ----
    // Per-bin counts and window totals <= 8640 < 2^16; prefix counts monotone
    // (b >= a per halfword), so packed 32-bit subtract/add never borrows/carries.
    const uint4* pa = (const uint4*)(g_H + ((size_t)r * TT1 + a) * NB);
    const uint4* pb = (const uint4*)(g_H + ((size_t)r * TT1 + b) * NB);
    uint4 A = pa[lane], B = pb[lane];
    unsigned dp[4] = {B.x - A.x, B.y - A.y, B.z - A.z, B.w - A.w};
    if ((j0 >> 3) == lane) dp[(j0 >> 1) & 3] += (unsigned)cL << ((j0 & 1) * 16);
    if ((jT >> 3) == lane) dp[(jT >> 1) & 3] += (unsigned)cR << ((jT & 1) * 16);
    unsigned uv = dp[0] + dp[1] + dp[2] + dp[3];
    int S = (int)((uv & 0xFFFFu) + (uv >> 16));   // this lane's 8-bin total

    int cum = S;
#pragma unroll
    for (int off = 1; off < 32; off <<= 1) {
        int t2 = __shfl_up_sync(0xffffffffu, cum, off);
        if (lane >= off) cum += t2;
    }
    unsigned bal = __ballot_sync(0xffffffffu, cum >= k + 1);
    int ln = __ffs(bal) - 1;
    int jstar = 0, base = 0, haj = 0, hbj = 0;
    if (lane == ln) {
        int run = cum - S;
        bool fnd = false;
        const unsigned* Aw = &A.x;
        const unsigned* Bw = &B.x;
#pragma unroll
        for (int t = 0; t < 8; t++) {
            int sh = (t & 1) * 16;
            int dt = (int)((dp[t >> 1] >> sh) & 0xFFFFu);
            int nr = run + dt;
            if (!fnd && nr >= k + 1) {
                jstar = lane * 8 + t;
                base = run;
                haj = (int)((Aw[t >> 1] >> sh) & 0xFFFFu);
                hbj = (int)((Bw[t >> 1] >> sh) & 0xFFFFu);
                fnd = true;
            }
            if (!fnd) run = nr;
        }
    }
    jstar = __shfl_sync(0xffffffffu, jstar, ln);
    base  = __shfl_sync(0xffffffffu, base,  ln);
    haj   = __shfl_sync(0xffffffffu, haj,   ln);
    hbj   = __shfl_sync(0xffffffffu, hbj,   ln);

    int r_in = k - base;                      // residual rank inside bucket jstar (with dups)
    int m = hbj - haj;                        // real slice length
    unsigned loS = g_bucketBase[r * (NB + 1) + jstar] + (unsigned)haj;
    int eL = (j0 == jstar) ? cL : 0;
    int eR = (jT == jstar) ? cR : 0;
    const float*          Ls = g_L   + r * TT + loS;
    const unsigned short* Is = g_Lid + r * TT + loS;

    __shared__ unsigned      hist[8][NB];
    __shared__ float         cand[8][32];
    __shared__ unsigned char subs[8][CAP];

    int jsh = jstar << 8;

    if (m <= CAP) {
#pragma unroll
        for (int q = 0; q < 8; q++) hist[warp][q * 32 + lane] = 0;
        __syncwarp();
        for (int t = lane; t < m; t += 32) {
            int sb = (int)Is[t] - jsh;
            subs[warp][t] = (unsigned char)sb;
            atomicAdd(&hist[warp][sb], 1u);
        }
        int sub0 = -1, subT = -1;
        if (eL > 0) sub0 = f0 - jsh;          // valid: j0 == jstar when eL > 0
        if (eR > 0) subT = fT - jsh;
        if (lane == 0) {
            if (eL > 0) atomicAdd(&hist[warp][sub0], (unsigned)eL);
            if (eR > 0) atomicAdd(&hist[warp][subT], (unsigned)eR);
        }
        __syncwarp();

        // ---- sub-bin scan (lane owns 8 bins; 2x LDS.128) ----
        const uint4* hp = (const uint4*)&hist[warp][lane * 8];
        uint4 h0 = hp[0], h1 = hp[1];
        int d2[8] = {(int)h0.x, (int)h0.y, (int)h0.z, (int)h0.w,
                     (int)h1.x, (int)h1.y, (int)h1.z, (int)h1.w};
        int S2 = d2[0] + d2[1] + d2[2] + d2[3] + d2[4] + d2[5] + d2[6] + d2[7];
        int cum2 = S2;
#pragma unroll
        for (int off = 1; off < 32; off <<= 1) {
            int t2 = __shfl_up_sync(0xffffffffu, cum2, off);
            if (lane >= off) cum2 += t2;
        }
        unsigned bal2 = __ballot_sync(0xffffffffu, cum2 >= r_in + 1);
        int ln2 = __ffs(bal2) - 1;
        int sstar = 0, base2 = 0;
        if (lane == ln2) {
            int run2 = cum2 - S2;
            bool fnd = false;
#pragma unroll
            for (int q = 0; q < 8; q++) {
                int nr = run2 + d2[q];
                if (!fnd && nr >= r_in + 1) { sstar = lane * 8 + q; base2 = run2; fnd = true; }
                if (!fnd) run2 = nr;
            }
        }
        sstar = __shfl_sync(0xffffffffu, sstar, ln2);
        base2 = __shfl_sync(0xffffffffu, base2, ln2);
        int r2 = r_in - base2;

        // ---- gather slice members of sub-bin sstar (byte compare) ----
        int cnt = 0;
        unsigned char sb8 = (unsigned char)sstar;
        for (int cc = 0; cc * 32 < m; cc++) {
            int idx = cc * 32 + lane;
            bool act = idx < m;
            bool match = act && (subs[warp][idx] == sb8);
            unsigned bm = __ballot_sync(0xffffffffu, match);
            int pos = cnt + __popc(bm & ((1u << lane) - 1u));
            if (match && pos < 32) cand[warp][pos] = Ls[idx];
            cnt += __popc(bm);
        }
        __syncwarp();

        if (cnt <= 32) {
            int vl = (eL > 0 && sub0 == sstar) ? eL : 0;
            int vr = (eR > 0 && subT == sstar) ? eR : 0;
            float c = (lane < cnt) ? cand[warp][lane] : 0.f;
            int lt = 0, eq = 0;
            for (int t = 0; t < cnt; t++) {
                float rv = cand[warp][t];
                lt += rv < c;
                eq += rv == c;
            }
            lt += vl * (x0 < c) + vr * (xT1 < c);
            eq += vl * (x0 == c) + vr * (xT1 == c);
            bool win = (lane < cnt) && (lt <= r2) && (r2 < lt + eq);
            unsigned bw = __ballot_sync(0xffffffffu, win);
            float ans = __shfl_sync(0xffffffffu, c, __ffs(bw) - 1);
            if (lane == 0) out[(size_t)r * n_out + i] = ans;
            return;
        }
        __syncwarp();
    }

    // ---- fallback: per-candidate counting over global slice (rare) ----
    float ans = 0.f;
    bool found = false;
    for (int cc = 0; cc * 32 < m && !found; cc++) {
        int idx = cc * 32 + lane;
        bool act = idx < m;
        float c = act ? Ls[idx] : 0.f;
        int lt = 0, eq = 0;
        for (int t = 0; t < m; t++) {
            float rv = Ls[t];
            lt += rv < c;
            eq += rv == c;
        }
        lt += eL * (x0 < c) + eR * (xT1 < c);
        eq += eL * (x0 == c) + eR * (xT1 == c);
        bool win = act && (lt <= r_in) && (r_in < lt + eq);
        unsigned bw = __ballot_sync(0xffffffffu, win);
        if (bw) { ans = __shfl_sync(0xffffffffu, c, __ffs(bw) - 1); found = true; }
    }
    if (lane == 0) out[(size_t)r * n_out + i] = ans;
}

// ---------- launch ----------
extern "C" void kernel_launch(void* const* d_in, const int* in_sizes, int n_in,
                              void* d_out, int out_size) {
    const float* att  = (const float*)d_in[0];
    const float* meta = (const float*)d_in[1];
    const float* w1   = (const float*)d_in[2];
    const float* b1   = (const float*)d_in[3];
    const float* w2   = (const float*)d_in[4];
    const float* b2   = (const float*)d_in[5];
    float* out = (float*)d_out;
    (void)in_sizes; (void)n_in;

    int n_out = out_size / RNUM;

    k_hist<<<RNUM * NSEG / 8 + 1, 256>>>(att, meta, w1, b1, w2, b2, n_out);
    k_scan<<<RNUM, 256>>>();
    k_fill<<<RNUM * NSEG, 256>>>(att);

    int total_warps = RNUM * n_out;
    int blocks = (total_warps + 7) / 8;
    k_select<<<blocks, 256>>>(att, out, n_out);
}